// round 1
// baseline (speedup 1.0000x reference)
#include <cuda_runtime.h>
#include <math.h>

// ---------------------------------------------------------------------------
// Problem dims (fixed): B=8, S=1024, D=768, H=12, hd=64
// ---------------------------------------------------------------------------
#define BS   8192        // B*S rows
#define DIM  768
#define D4   3072        // 4*D
#define QKVN 2304        // 3*D
#define NH   12
#define HD   64
#define SEQ  1024
#define LN_EPS 1e-5f

// ---------------------------------------------------------------------------
// Static device scratch (no allocations allowed)
// ---------------------------------------------------------------------------
__device__ float g_xn  [BS * DIM];    // ln1 output (residual 1)
__device__ float g_qkv [BS * QKVN];   // fused qkv: col = t*768 + h*64 + k
__device__ float g_att [BS * DIM];    // attention output, concat heads
__device__ float g_y1  [BS * DIM];    // after o-proj + residual
__device__ float g_y2  [BS * DIM];    // ln2 output (residual 2)
__device__ float g_h   [BS * D4];     // ffn hidden
__device__ float g_wqkv[DIM * QKVN];  // repacked [D, 3D]
__device__ float g_bqkv[QKVN];

// ---------------------------------------------------------------------------
// Repack Wq/Wk/Wv [H,D,hd] -> Wqkv [D, 3D] with col = t*768 + h*64 + k
// ---------------------------------------------------------------------------
__global__ void repack_qkv_kernel(const float* __restrict__ Wq, const float* __restrict__ bq,
                                  const float* __restrict__ Wk, const float* __restrict__ bk,
                                  const float* __restrict__ Wv, const float* __restrict__ bv) {
    int idx = blockIdx.x * blockDim.x + threadIdx.x;
    const int total = DIM * QKVN;
    if (idx < total) {
        int d   = idx / QKVN;
        int col = idx % QKVN;
        int t   = col / DIM;
        int h   = (col % DIM) / HD;
        int kk  = col % HD;
        const float* W = (t == 0) ? Wq : (t == 1) ? Wk : Wv;
        g_wqkv[idx] = W[(h * DIM + d) * HD + kk];
    }
    if (idx < QKVN) {
        int t  = idx / DIM;
        int h  = (idx % DIM) / HD;
        int kk = idx % HD;
        const float* bb = (t == 0) ? bq : (t == 1) ? bk : bv;
        g_bqkv[idx] = bb[h * HD + kk];
    }
}

// ---------------------------------------------------------------------------
// LayerNorm with ddof=1 (torch.var unbiased), one block per row of 768
// ---------------------------------------------------------------------------
__global__ void layernorm_kernel(const float* __restrict__ X,
                                 const float* __restrict__ gamma,
                                 const float* __restrict__ beta,
                                 float* __restrict__ Y) {
    const int row = blockIdx.x;
    const float* x = X + (size_t)row * DIM;
    float*       y = Y + (size_t)row * DIM;
    __shared__ float red[256];
    int tid = threadIdx.x;

    float s = 0.f;
    for (int i = tid; i < DIM; i += 256) s += x[i];
    red[tid] = s; __syncthreads();
    for (int off = 128; off > 0; off >>= 1) {
        if (tid < off) red[tid] += red[tid + off];
        __syncthreads();
    }
    float mean = red[0] / (float)DIM;
    __syncthreads();

    float v = 0.f;
    for (int i = tid; i < DIM; i += 256) { float d = x[i] - mean; v += d * d; }
    red[tid] = v; __syncthreads();
    for (int off = 128; off > 0; off >>= 1) {
        if (tid < off) red[tid] += red[tid + off];
        __syncthreads();
    }
    float var = red[0] / (float)(DIM - 1);      // ddof = 1
    float inv = rsqrtf(var + LN_EPS);

    for (int i = tid; i < DIM; i += 256)
        y[i] = gamma[i] * (x[i] - mean) * inv + beta[i];
}

// ---------------------------------------------------------------------------
// Tiled SGEMM: C[M,N] = A[M,K] @ B[K,N] + bias[N]  (+ GELU) (+ residual)
// BM=BN=128, BK=8, 256 threads, 8x8 microtile. M,N,K multiples of tile dims.
// ---------------------------------------------------------------------------
template <bool GELU, bool RES>
__global__ void sgemm_kernel(const float* __restrict__ A,
                             const float* __restrict__ B,
                             const float* __restrict__ bias,
                             const float* __restrict__ res,
                             float* __restrict__ C,
                             int M, int N, int K) {
    __shared__ __align__(16) float As[8][128];
    __shared__ __align__(16) float Bs[8][128];

    const int tid  = threadIdx.x;
    const int brow = blockIdx.y * 128;
    const int bcol = blockIdx.x * 128;

    const int a_row  = tid >> 1;          // 0..127
    const int a_col4 = (tid & 1) * 4;     // 0 or 4
    const int b_row  = tid >> 5;          // 0..7
    const int b_col4 = (tid & 31) * 4;

    const int tr = (tid >> 4) * 8;        // row offset in tile
    const int tc = (tid & 15) * 8;        // col offset in tile

    float acc[8][8];
#pragma unroll
    for (int i = 0; i < 8; i++)
#pragma unroll
        for (int j = 0; j < 8; j++) acc[i][j] = 0.f;

    const float* Aptr = A + (size_t)(brow + a_row) * K + a_col4;
    const float* Bptr = B + (size_t)b_row * N + bcol + b_col4;

    for (int k0 = 0; k0 < K; k0 += 8) {
        float4 av = *(const float4*)(Aptr + k0);
        As[a_col4 + 0][a_row] = av.x;
        As[a_col4 + 1][a_row] = av.y;
        As[a_col4 + 2][a_row] = av.z;
        As[a_col4 + 3][a_row] = av.w;
        float4 bv = *(const float4*)(Bptr + (size_t)k0 * N);
        *(float4*)&Bs[b_row][b_col4] = bv;
        __syncthreads();

#pragma unroll
        for (int k = 0; k < 8; k++) {
            float4 a0 = *(const float4*)&As[k][tr];
            float4 a1 = *(const float4*)&As[k][tr + 4];
            float4 b0 = *(const float4*)&Bs[k][tc];
            float4 b1 = *(const float4*)&Bs[k][tc + 4];
            float ra[8] = {a0.x, a0.y, a0.z, a0.w, a1.x, a1.y, a1.z, a1.w};
            float rb[8] = {b0.x, b0.y, b0.z, b0.w, b1.x, b1.y, b1.z, b1.w};
#pragma unroll
            for (int i = 0; i < 8; i++)
#pragma unroll
                for (int j = 0; j < 8; j++)
                    acc[i][j] = fmaf(ra[i], rb[j], acc[i][j]);
        }
        __syncthreads();
    }

    // epilogue
#pragma unroll
    for (int i = 0; i < 8; i++) {
        int row = brow + tr + i;
#pragma unroll
        for (int j = 0; j < 8; j++) {
            int col = bcol + tc + j;
            float c = acc[i][j] + bias[col];
            if (GELU) c = 0.5f * c * (1.0f + erff(c * 0.70710678118654752f));
            if (RES)  c += res[(size_t)row * N + col];
            C[(size_t)row * N + col] = c;
        }
    }
}

// ---------------------------------------------------------------------------
// Flash-style attention. Grid (S/64, H, B), 64 threads, thread = 1 query row.
// Q/K/V read from fused qkv buffer; output concat-head layout [BS, D].
// ---------------------------------------------------------------------------
__global__ __launch_bounds__(64) void attention_kernel(const float* __restrict__ qkv,
                                                       float* __restrict__ out) {
    const int b  = blockIdx.z;
    const int h  = blockIdx.y;
    const int qt = blockIdx.x;
    const int t  = threadIdx.x;                 // 0..63
    const int m  = b * SEQ + qt * 64 + t;       // global row

    const float* qp = qkv + (size_t)m * QKVN + h * HD;
    float q[HD];
#pragma unroll
    for (int d = 0; d < HD; d++) q[d] = qp[d];

    float o[HD];
#pragma unroll
    for (int d = 0; d < HD; d++) o[d] = 0.f;
    float mrun = -INFINITY, lrun = 0.f;

    __shared__ __align__(16) float Ks[32][HD];
    __shared__ __align__(16) float Vs[32][HD];

    const float* Kbase = qkv + (size_t)b * SEQ * QKVN + DIM     + h * HD;
    const float* Vbase = qkv + (size_t)b * SEQ * QKVN + 2 * DIM + h * HD;
    const float scale = 0.125f;                 // 1/sqrt(64)

    for (int s0 = 0; s0 < SEQ; s0 += 32) {
        __syncthreads();
        for (int idx = t; idx < 32 * HD; idx += 64) {
            int j = idx >> 6, d = idx & 63;
            Ks[j][d] = Kbase[(size_t)(s0 + j) * QKVN + d];
            Vs[j][d] = Vbase[(size_t)(s0 + j) * QKVN + d];
        }
        __syncthreads();

        float p[32];
        float tmax = mrun;
#pragma unroll 4
        for (int j = 0; j < 32; j++) {
            const float4* k4 = (const float4*)&Ks[j][0];
            float sc = 0.f;
#pragma unroll
            for (int dd = 0; dd < 16; dd++) {
                float4 kv = k4[dd];
                sc = fmaf(q[4 * dd + 0], kv.x, sc);
                sc = fmaf(q[4 * dd + 1], kv.y, sc);
                sc = fmaf(q[4 * dd + 2], kv.z, sc);
                sc = fmaf(q[4 * dd + 3], kv.w, sc);
            }
            sc *= scale;
            p[j] = sc;
            tmax = fmaxf(tmax, sc);
        }

        float alpha = expf(mrun - tmax);
        lrun *= alpha;
#pragma unroll
        for (int d = 0; d < HD; d++) o[d] *= alpha;

#pragma unroll 4
        for (int j = 0; j < 32; j++) {
            float pj = expf(p[j] - tmax);
            lrun += pj;
            const float4* v4 = (const float4*)&Vs[j][0];
#pragma unroll
            for (int dd = 0; dd < 16; dd++) {
                float4 vv = v4[dd];
                o[4 * dd + 0] = fmaf(pj, vv.x, o[4 * dd + 0]);
                o[4 * dd + 1] = fmaf(pj, vv.y, o[4 * dd + 1]);
                o[4 * dd + 2] = fmaf(pj, vv.z, o[4 * dd + 2]);
                o[4 * dd + 3] = fmaf(pj, vv.w, o[4 * dd + 3]);
            }
        }
        mrun = tmax;
    }

    float inv = 1.f / lrun;
    float* op = out + (size_t)m * DIM + h * HD;
#pragma unroll
    for (int d = 0; d < HD; d++) op[d] = o[d] * inv;
}

// ---------------------------------------------------------------------------
// Host launch
// ---------------------------------------------------------------------------
extern "C" void kernel_launch(void* const* d_in, const int* in_sizes, int n_in,
                              void* d_out, int out_size) {
    const float* x   = (const float*)d_in[0];
    const float* Wq  = (const float*)d_in[1];
    const float* bq  = (const float*)d_in[2];
    const float* Wk  = (const float*)d_in[3];
    const float* bk  = (const float*)d_in[4];
    const float* Wv  = (const float*)d_in[5];
    const float* bv  = (const float*)d_in[6];
    const float* Wo  = (const float*)d_in[7];
    const float* bo  = (const float*)d_in[8];
    const float* W1  = (const float*)d_in[9];
    const float* b1  = (const float*)d_in[10];
    const float* W2  = (const float*)d_in[11];
    const float* b2  = (const float*)d_in[12];
    const float* g1  = (const float*)d_in[13];
    const float* be1 = (const float*)d_in[14];
    const float* g2  = (const float*)d_in[15];
    const float* be2 = (const float*)d_in[16];
    float* out = (float*)d_out;

    float *xn, *qkv, *att, *y1, *y2, *hbuf, *wqkv, *bqkv;
    cudaGetSymbolAddress((void**)&xn,   g_xn);
    cudaGetSymbolAddress((void**)&qkv,  g_qkv);
    cudaGetSymbolAddress((void**)&att,  g_att);
    cudaGetSymbolAddress((void**)&y1,   g_y1);
    cudaGetSymbolAddress((void**)&y2,   g_y2);
    cudaGetSymbolAddress((void**)&hbuf, g_h);
    cudaGetSymbolAddress((void**)&wqkv, g_wqkv);
    cudaGetSymbolAddress((void**)&bqkv, g_bqkv);

    // 1. repack qkv weights
    {
        int total = DIM * QKVN;
        repack_qkv_kernel<<<(total + 255) / 256, 256>>>(Wq, bq, Wk, bk, Wv, bv);
    }
    // 2. ln1
    layernorm_kernel<<<BS, 256>>>(x, g1, be1, xn);
    // 3. fused QKV gemm: [8192,2304] = xn @ wqkv + bqkv
    {
        dim3 grid(QKVN / 128, BS / 128);
        sgemm_kernel<false, false><<<grid, 256>>>(xn, wqkv, bqkv, nullptr, qkv, BS, QKVN, DIM);
    }
    // 4. attention
    {
        dim3 grid(SEQ / 64, NH, 8);
        attention_kernel<<<grid, 64>>>(qkv, att);
    }
    // 5. o-proj + residual(xn): y1 = att @ Wo + bo + xn
    {
        dim3 grid(DIM / 128, BS / 128);
        sgemm_kernel<false, true><<<grid, 256>>>(att, Wo, bo, xn, y1, BS, DIM, DIM);
    }
    // 6. ln2
    layernorm_kernel<<<BS, 256>>>(y1, g2, be2, y2);
    // 7. ffn up + gelu: h = gelu(y2 @ W1 + b1)
    {
        dim3 grid(D4 / 128, BS / 128);
        sgemm_kernel<true, false><<<grid, 256>>>(y2, W1, b1, nullptr, hbuf, BS, D4, DIM);
    }
    // 8. ffn down + residual(y2): out = h @ W2 + b2 + y2
    {
        dim3 grid(DIM / 128, BS / 128);
        sgemm_kernel<false, true><<<grid, 256>>>(hbuf, W2, b2, y2, out, BS, DIM, D4);
    }
}

// round 3
// speedup vs baseline: 2.1494x; 2.1494x over previous
#include <cuda_runtime.h>
#include <math.h>
#include <stdint.h>

// ---------------------------------------------------------------------------
// Problem dims (fixed): B=8, S=1024, D=768, H=12, hd=64
// ---------------------------------------------------------------------------
#define BS   8192        // B*S rows
#define DIM  768
#define D4   3072        // 4*D
#define QKVN 2304        // 3*D
#define NH   12
#define HD   64
#define SEQ  1024
#define LN_EPS 1e-5f

// ---------------------------------------------------------------------------
// Static device scratch (no allocations allowed)
// ---------------------------------------------------------------------------
__device__ float g_xn  [BS * DIM];     // ln1 output (residual 1)
__device__ float g_qkv [BS * QKVN];    // fused qkv: col = t*768 + h*64 + k
__device__ float g_att [BS * DIM];     // attention out, concat heads
__device__ float g_y1  [BS * DIM];     // after o-proj + residual
__device__ float g_y2  [BS * DIM];     // ln2 output (residual 2)
__device__ float g_h   [BS * D4];      // ffn hidden
__device__ float g_wqkv_t[QKVN * DIM]; // [N=2304, K=768]
__device__ float g_bqkv[QKVN];
__device__ float g_wo_t[DIM * DIM];    // [N=768, K=768]
__device__ float g_w1_t[D4 * DIM];     // [N=3072, K=768]
__device__ float g_w2_t[DIM * D4];     // [N=768, K=3072]

// ---------------------------------------------------------------------------
// Warp-level tf32 tensor-core GEMM:
//   C[M,N] = A[M,K] @ Bt[N,K]^T + bias (+GELU) (+res)
// CTA tile 128x128, BK=32, 8 warps (2m x 4n), warp tile 64x32,
// mma.sync.m16n8k8.tf32, cp.async double buffering.
// Smem row stride 36 floats => fragment loads hit all 32 banks.
// ---------------------------------------------------------------------------
#define SM_STRIDE 36
#define TILE_FLOATS (128 * SM_STRIDE)
#define GEMM_SMEM_BYTES (4 * TILE_FLOATS * 4)   // 2 stages x (A+B) = 73728

__device__ __forceinline__ uint32_t f2tf32(float v) {
    uint32_t r;
    asm("cvt.rna.tf32.f32 %0, %1;" : "=r"(r) : "f"(v));
    return r;
}

__device__ __forceinline__ uint32_t smem_u32(const void* p) {
    uint32_t a;
    asm("{ .reg .u64 t; cvta.to.shared.u64 t, %1; cvt.u32.u64 %0, t; }"
        : "=r"(a) : "l"(p));
    return a;
}

template <bool GELU, bool RES>
__global__ __launch_bounds__(256) void mma_gemm_kernel(
    const float* __restrict__ A, const float* __restrict__ Bt,
    const float* __restrict__ bias, const float* __restrict__ res,
    float* __restrict__ C, int M, int N, int K) {
    extern __shared__ __align__(16) float sm[];
    float* Asm = sm;                     // [2][128][36]
    float* Bsm = sm + 2 * TILE_FLOATS;   // [2][128][36]

    const int tid  = threadIdx.x;
    const int wid  = tid >> 5;
    const int lane = tid & 31;
    const int g    = lane >> 2;          // 0..7
    const int t4   = lane & 3;           // 0..3
    const int wm   = (wid >> 2) * 64;    // 0 / 64
    const int wn   = (wid & 3) * 32;     // 0/32/64/96

    const int brow = blockIdx.y * 128;
    const int bcol = blockIdx.x * 128;
    const int NCH  = K >> 5;             // K chunks of 32

    float acc[4][4][4];
#pragma unroll
    for (int mt = 0; mt < 4; mt++)
#pragma unroll
        for (int nt = 0; nt < 4; nt++)
#pragma unroll
            for (int r = 0; r < 4; r++) acc[mt][nt][r] = 0.f;

    const uint32_t sA = smem_u32(Asm);
    const uint32_t sB = smem_u32(Bsm);

    auto load_tile = [&](int chunk, int s) {
        const int k0 = chunk * 32;
#pragma unroll
        for (int it = 0; it < 4; it++) {
            int id  = it * 256 + tid;       // 0..1023
            int row = id >> 3;              // 0..127
            int cc  = id & 7;               // 16B chunk in 128B row
            uint32_t off = (uint32_t)((s * TILE_FLOATS + row * SM_STRIDE + cc * 4) * 4);
            const float* ga = A + (size_t)(brow + row) * K + k0 + cc * 4;
            asm volatile("cp.async.cg.shared.global [%0], [%1], 16;"
                         :: "r"(sA + off), "l"(ga));
            const float* gb = Bt + (size_t)(bcol + row) * K + k0 + cc * 4;
            asm volatile("cp.async.cg.shared.global [%0], [%1], 16;"
                         :: "r"(sB + off), "l"(gb));
        }
        asm volatile("cp.async.commit_group;" ::: "memory");
    };

    load_tile(0, 0);
    load_tile(1, 1);

    for (int i = 0; i < NCH; i++) {
        const int s = i & 1;
        if (i < NCH - 1) asm volatile("cp.async.wait_group 1;" ::: "memory");
        else             asm volatile("cp.async.wait_group 0;" ::: "memory");
        __syncthreads();

        const float* as = Asm + s * TILE_FLOATS;
        const float* bs = Bsm + s * TILE_FLOATS;

#pragma unroll
        for (int kk = 0; kk < 4; kk++) {       // 4 k-steps of 8
            const int k0 = kk * 8;
            uint32_t af[4][4];
#pragma unroll
            for (int mt = 0; mt < 4; mt++) {
                const float* p = as + (wm + mt * 16 + g) * SM_STRIDE + k0 + t4;
                af[mt][0] = f2tf32(p[0]);
                af[mt][1] = f2tf32(p[8 * SM_STRIDE]);
                af[mt][2] = f2tf32(p[4]);
                af[mt][3] = f2tf32(p[8 * SM_STRIDE + 4]);
            }
            uint32_t bf[4][2];
#pragma unroll
            for (int nt = 0; nt < 4; nt++) {
                const float* p = bs + (wn + nt * 8 + g) * SM_STRIDE + k0 + t4;
                bf[nt][0] = f2tf32(p[0]);
                bf[nt][1] = f2tf32(p[4]);
            }
#pragma unroll
            for (int mt = 0; mt < 4; mt++)
#pragma unroll
                for (int nt = 0; nt < 4; nt++) {
                    asm volatile(
                        "mma.sync.aligned.m16n8k8.row.col.f32.tf32.tf32.f32 "
                        "{%0,%1,%2,%3}, {%4,%5,%6,%7}, {%8,%9}, {%0,%1,%2,%3};"
                        : "+f"(acc[mt][nt][0]), "+f"(acc[mt][nt][1]),
                          "+f"(acc[mt][nt][2]), "+f"(acc[mt][nt][3])
                        : "r"(af[mt][0]), "r"(af[mt][1]), "r"(af[mt][2]), "r"(af[mt][3]),
                          "r"(bf[nt][0]), "r"(bf[nt][1]));
                }
        }
        __syncthreads();
        if (i + 2 < NCH) load_tile(i + 2, s);
    }

    // epilogue: bias (+GELU) (+res), float2 stores
#pragma unroll
    for (int mt = 0; mt < 4; mt++) {
        const int row0 = brow + wm + mt * 16 + g;
#pragma unroll
        for (int nt = 0; nt < 4; nt++) {
            const int col = bcol + wn + nt * 8 + t4 * 2;
            const float bx = bias[col], by = bias[col + 1];
#pragma unroll
            for (int hh = 0; hh < 2; hh++) {
                const int row = row0 + hh * 8;
                float vx = acc[mt][nt][2 * hh]     + bx;
                float vy = acc[mt][nt][2 * hh + 1] + by;
                if (GELU) {
                    vx = 0.5f * vx * (1.0f + erff(vx * 0.70710678118654752f));
                    vy = 0.5f * vy * (1.0f + erff(vy * 0.70710678118654752f));
                }
                size_t go = (size_t)row * N + col;
                if (RES) {
                    float2 rv = *(const float2*)&res[go];
                    vx += rv.x; vy += rv.y;
                }
                float2 o; o.x = vx; o.y = vy;
                *(float2*)&C[go] = o;
            }
        }
    }
}

// ---------------------------------------------------------------------------
// Repack Wq/Wk/Wv [H,D,hd] -> Wqkv_t [3D, D]  (row n = output col, K contig)
// ---------------------------------------------------------------------------
__global__ void repack_qkv_t_kernel(const float* __restrict__ Wq, const float* __restrict__ bq,
                                    const float* __restrict__ Wk, const float* __restrict__ bk,
                                    const float* __restrict__ Wv, const float* __restrict__ bv) {
    int idx = blockIdx.x * blockDim.x + threadIdx.x;
    const int total = QKVN * DIM;
    if (idx < total) {
        int n = idx / DIM;
        int d = idx % DIM;
        int t  = n / DIM;
        int h  = (n % DIM) / HD;
        int kk = n % HD;
        const float* W = (t == 0) ? Wq : (t == 1) ? Wk : Wv;
        g_wqkv_t[idx] = W[(h * DIM + d) * HD + kk];
    }
    if (idx < QKVN) {
        int t  = idx / DIM;
        int h  = (idx % DIM) / HD;
        int kk = idx % HD;
        const float* bb = (t == 0) ? bq : (t == 1) ? bk : bv;
        g_bqkv[idx] = bb[h * HD + kk];
    }
}

// Tiled transpose: in[R,C] -> out[C,R]
__global__ void transpose_kernel(const float* __restrict__ in, float* __restrict__ out,
                                 int R, int C) {
    __shared__ float t[32][33];
    int c0 = blockIdx.x * 32, r0 = blockIdx.y * 32;
    int x = c0 + threadIdx.x;
    for (int dy = threadIdx.y; dy < 32; dy += 8) {
        int r = r0 + dy;
        if (r < R && x < C) t[dy][threadIdx.x] = in[(size_t)r * C + x];
    }
    __syncthreads();
    int y = r0 + threadIdx.x;
    for (int dx = threadIdx.y; dx < 32; dx += 8) {
        int c = c0 + dx;
        if (c < C && y < R) out[(size_t)c * R + y] = t[threadIdx.x][dx];
    }
}

// ---------------------------------------------------------------------------
// LayerNorm with ddof=1, one block per row of 768
// ---------------------------------------------------------------------------
__global__ void layernorm_kernel(const float* __restrict__ X,
                                 const float* __restrict__ gamma,
                                 const float* __restrict__ beta,
                                 float* __restrict__ Y) {
    const int row = blockIdx.x;
    const float* x = X + (size_t)row * DIM;
    float*       y = Y + (size_t)row * DIM;
    __shared__ float red[256];
    int tid = threadIdx.x;

    float s = 0.f;
    for (int i = tid; i < DIM; i += 256) s += x[i];
    red[tid] = s; __syncthreads();
    for (int off = 128; off > 0; off >>= 1) {
        if (tid < off) red[tid] += red[tid + off];
        __syncthreads();
    }
    float mean = red[0] / (float)DIM;
    __syncthreads();

    float v = 0.f;
    for (int i = tid; i < DIM; i += 256) { float d = x[i] - mean; v += d * d; }
    red[tid] = v; __syncthreads();
    for (int off = 128; off > 0; off >>= 1) {
        if (tid < off) red[tid] += red[tid + off];
        __syncthreads();
    }
    float var = red[0] / (float)(DIM - 1);      // ddof = 1
    float inv = rsqrtf(var + LN_EPS);

    for (int i = tid; i < DIM; i += 256)
        y[i] = gamma[i] * (x[i] - mean) * inv + beta[i];
}

// ---------------------------------------------------------------------------
// Flash-style attention (unchanged). Grid (S/64, H, B), 64 threads.
// ---------------------------------------------------------------------------
__global__ __launch_bounds__(64) void attention_kernel(const float* __restrict__ qkv,
                                                       float* __restrict__ out) {
    const int b  = blockIdx.z;
    const int h  = blockIdx.y;
    const int qt = blockIdx.x;
    const int t  = threadIdx.x;
    const int m  = b * SEQ + qt * 64 + t;

    const float* qp = qkv + (size_t)m * QKVN + h * HD;
    float q[HD];
#pragma unroll
    for (int d = 0; d < HD; d++) q[d] = qp[d];

    float o[HD];
#pragma unroll
    for (int d = 0; d < HD; d++) o[d] = 0.f;
    float mrun = -INFINITY, lrun = 0.f;

    __shared__ __align__(16) float Ks[32][HD];
    __shared__ __align__(16) float Vs[32][HD];

    const float* Kbase = qkv + (size_t)b * SEQ * QKVN + DIM     + h * HD;
    const float* Vbase = qkv + (size_t)b * SEQ * QKVN + 2 * DIM + h * HD;
    const float scale = 0.125f;

    for (int s0 = 0; s0 < SEQ; s0 += 32) {
        __syncthreads();
        for (int idx = t; idx < 32 * HD; idx += 64) {
            int j = idx >> 6, d = idx & 63;
            Ks[j][d] = Kbase[(size_t)(s0 + j) * QKVN + d];
            Vs[j][d] = Vbase[(size_t)(s0 + j) * QKVN + d];
        }
        __syncthreads();

        float p[32];
        float tmax = mrun;
#pragma unroll 4
        for (int j = 0; j < 32; j++) {
            const float4* k4 = (const float4*)&Ks[j][0];
            float sc = 0.f;
#pragma unroll
            for (int dd = 0; dd < 16; dd++) {
                float4 kv = k4[dd];
                sc = fmaf(q[4 * dd + 0], kv.x, sc);
                sc = fmaf(q[4 * dd + 1], kv.y, sc);
                sc = fmaf(q[4 * dd + 2], kv.z, sc);
                sc = fmaf(q[4 * dd + 3], kv.w, sc);
            }
            sc *= scale;
            p[j] = sc;
            tmax = fmaxf(tmax, sc);
        }

        float alpha = expf(mrun - tmax);
        lrun *= alpha;
#pragma unroll
        for (int d = 0; d < HD; d++) o[d] *= alpha;

#pragma unroll 4
        for (int j = 0; j < 32; j++) {
            float pj = expf(p[j] - tmax);
            lrun += pj;
            const float4* v4 = (const float4*)&Vs[j][0];
#pragma unroll
            for (int dd = 0; dd < 16; dd++) {
                float4 vv = v4[dd];
                o[4 * dd + 0] = fmaf(pj, vv.x, o[4 * dd + 0]);
                o[4 * dd + 1] = fmaf(pj, vv.y, o[4 * dd + 1]);
                o[4 * dd + 2] = fmaf(pj, vv.z, o[4 * dd + 2]);
                o[4 * dd + 3] = fmaf(pj, vv.w, o[4 * dd + 3]);
            }
        }
        mrun = tmax;
    }

    float inv = 1.f / lrun;
    float* op = out + (size_t)m * DIM + h * HD;
#pragma unroll
    for (int d = 0; d < HD; d++) op[d] = o[d] * inv;
}

// ---------------------------------------------------------------------------
// Host launch
// ---------------------------------------------------------------------------
extern "C" void kernel_launch(void* const* d_in, const int* in_sizes, int n_in,
                              void* d_out, int out_size) {
    const float* x   = (const float*)d_in[0];
    const float* Wq  = (const float*)d_in[1];
    const float* bq  = (const float*)d_in[2];
    const float* Wk  = (const float*)d_in[3];
    const float* bk  = (const float*)d_in[4];
    const float* Wv  = (const float*)d_in[5];
    const float* bv  = (const float*)d_in[6];
    const float* Wo  = (const float*)d_in[7];
    const float* bo  = (const float*)d_in[8];
    const float* W1  = (const float*)d_in[9];
    const float* b1  = (const float*)d_in[10];
    const float* W2  = (const float*)d_in[11];
    const float* b2  = (const float*)d_in[12];
    const float* g1  = (const float*)d_in[13];
    const float* be1 = (const float*)d_in[14];
    const float* g2  = (const float*)d_in[15];
    const float* be2 = (const float*)d_in[16];
    float* out = (float*)d_out;

    float *xn, *qkv, *att, *y1, *y2, *hbuf, *wqkv_t, *bqkv, *wo_t, *w1_t, *w2_t;
    cudaGetSymbolAddress((void**)&xn,     g_xn);
    cudaGetSymbolAddress((void**)&qkv,    g_qkv);
    cudaGetSymbolAddress((void**)&att,    g_att);
    cudaGetSymbolAddress((void**)&y1,     g_y1);
    cudaGetSymbolAddress((void**)&y2,     g_y2);
    cudaGetSymbolAddress((void**)&hbuf,   g_h);
    cudaGetSymbolAddress((void**)&wqkv_t, g_wqkv_t);
    cudaGetSymbolAddress((void**)&bqkv,   g_bqkv);
    cudaGetSymbolAddress((void**)&wo_t,   g_wo_t);
    cudaGetSymbolAddress((void**)&w1_t,   g_w1_t);
    cudaGetSymbolAddress((void**)&w2_t,   g_w2_t);

    cudaFuncSetAttribute(mma_gemm_kernel<false, false>,
                         cudaFuncAttributeMaxDynamicSharedMemorySize, GEMM_SMEM_BYTES);
    cudaFuncSetAttribute(mma_gemm_kernel<false, true>,
                         cudaFuncAttributeMaxDynamicSharedMemorySize, GEMM_SMEM_BYTES);
    cudaFuncSetAttribute(mma_gemm_kernel<true, false>,
                         cudaFuncAttributeMaxDynamicSharedMemorySize, GEMM_SMEM_BYTES);

    // weight repacks (small; stay hot in L2)
    {
        int total = QKVN * DIM;
        repack_qkv_t_kernel<<<(total + 255) / 256, 256>>>(Wq, bq, Wk, bk, Wv, bv);
    }
    {
        dim3 blk(32, 8);
        transpose_kernel<<<dim3(DIM / 32, DIM / 32), blk>>>(Wo, wo_t, DIM, DIM);
        transpose_kernel<<<dim3(D4 / 32, DIM / 32), blk>>>(W1, w1_t, DIM, D4);
        transpose_kernel<<<dim3(DIM / 32, D4 / 32), blk>>>(W2, w2_t, D4, DIM);
    }

    // 1. ln1
    layernorm_kernel<<<BS, 256>>>(x, g1, be1, xn);
    // 2. fused QKV gemm
    mma_gemm_kernel<false, false><<<dim3(QKVN / 128, BS / 128), 256, GEMM_SMEM_BYTES>>>(
        xn, wqkv_t, bqkv, nullptr, qkv, BS, QKVN, DIM);
    // 3. attention
    attention_kernel<<<dim3(SEQ / 64, NH, 8), 64>>>(qkv, att);
    // 4. o-proj + residual
    mma_gemm_kernel<false, true><<<dim3(DIM / 128, BS / 128), 256, GEMM_SMEM_BYTES>>>(
        att, wo_t, bo, xn, y1, BS, DIM, DIM);
    // 5. ln2
    layernorm_kernel<<<BS, 256>>>(y1, g2, be2, y2);
    // 6. ffn up + gelu
    mma_gemm_kernel<true, false><<<dim3(D4 / 128, BS / 128), 256, GEMM_SMEM_BYTES>>>(
        y2, w1_t, b1, nullptr, hbuf, BS, D4, DIM);
    // 7. ffn down + residual
    mma_gemm_kernel<false, true><<<dim3(DIM / 128, BS / 128), 256, GEMM_SMEM_BYTES>>>(
        hbuf, w2_t, b2, y2, out, BS, DIM, D4);
}

// round 5
// speedup vs baseline: 3.2990x; 1.5349x over previous
#include <cuda_runtime.h>
#include <math.h>
#include <stdint.h>

// ---------------------------------------------------------------------------
// Problem dims (fixed): B=8, S=1024, D=768, H=12, hd=64
// ---------------------------------------------------------------------------
#define BS   8192        // B*S rows
#define DIM  768
#define D4   3072        // 4*D
#define QKVN 2304        // 3*D
#define NH   12
#define HD   64
#define SEQ  1024
#define LN_EPS 1e-5f

// ---------------------------------------------------------------------------
// Static device scratch (no allocations allowed)
// ---------------------------------------------------------------------------
__device__ float g_xn  [BS * DIM];     // ln1 output (residual 1)
__device__ float g_qkv [BS * QKVN];    // fused qkv: col = t*768 + h*64 + k
__device__ float g_att [BS * DIM];     // attention out, concat heads
__device__ float g_y1  [BS * DIM];     // after o-proj + residual
__device__ float g_y2  [BS * DIM];     // ln2 output (residual 2)
__device__ float g_h   [BS * D4];      // ffn hidden
__device__ float g_wqkv_t[QKVN * DIM]; // [N=2304, K=768]
__device__ float g_bqkv[QKVN];
__device__ float g_wo_t[DIM * DIM];    // [N=768, K=768]
__device__ float g_w1_t[D4 * DIM];     // [N=3072, K=768]
__device__ float g_w2_t[DIM * D4];     // [N=768, K=3072]

__device__ __forceinline__ uint32_t f2tf32(float v) {
    uint32_t r;
    asm("cvt.rna.tf32.f32 %0, %1;" : "=r"(r) : "f"(v));
    return r;
}

__device__ __forceinline__ uint32_t smem_u32(const void* p) {
    uint32_t a;
    asm("{ .reg .u64 t; cvta.to.shared.u64 t, %1; cvt.u32.u64 %0, t; }"
        : "=r"(a) : "l"(p));
    return a;
}

#define MMA_TF32(acc, a, b0, b1)                                               \
    asm volatile(                                                              \
        "mma.sync.aligned.m16n8k8.row.col.f32.tf32.tf32.f32 "                  \
        "{%0,%1,%2,%3}, {%4,%5,%6,%7}, {%8,%9}, {%0,%1,%2,%3};"                \
        : "+f"((acc)[0]), "+f"((acc)[1]), "+f"((acc)[2]), "+f"((acc)[3])       \
        : "r"((a)[0]), "r"((a)[1]), "r"((a)[2]), "r"((a)[3]),                  \
          "r"(b0), "r"(b1))

// ---------------------------------------------------------------------------
// Warp-level tf32 tensor-core GEMM:
//   C[M,N] = A[M,K] @ Bt[N,K]^T + bias (+GELU) (+res)
// CTA tile 128x128, BK=32, 8 warps, warp tile 64x32, cp.async double buffer.
// ---------------------------------------------------------------------------
#define SM_STRIDE 36
#define TILE_FLOATS (128 * SM_STRIDE)
#define GEMM_SMEM_BYTES (4 * TILE_FLOATS * 4)

template <bool GELU, bool RES>
__global__ __launch_bounds__(256) void mma_gemm_kernel(
    const float* __restrict__ A, const float* __restrict__ Bt,
    const float* __restrict__ bias, const float* __restrict__ res,
    float* __restrict__ C, int M, int N, int K) {
    extern __shared__ __align__(16) float sm[];
    float* Asm = sm;
    float* Bsm = sm + 2 * TILE_FLOATS;

    const int tid  = threadIdx.x;
    const int wid  = tid >> 5;
    const int lane = tid & 31;
    const int g    = lane >> 2;
    const int t4   = lane & 3;
    const int wm   = (wid >> 2) * 64;
    const int wn   = (wid & 3) * 32;

    const int brow = blockIdx.y * 128;
    const int bcol = blockIdx.x * 128;
    const int NCH  = K >> 5;

    float acc[4][4][4];
#pragma unroll
    for (int mt = 0; mt < 4; mt++)
#pragma unroll
        for (int nt = 0; nt < 4; nt++)
#pragma unroll
            for (int r = 0; r < 4; r++) acc[mt][nt][r] = 0.f;

    const uint32_t sA = smem_u32(Asm);
    const uint32_t sB = smem_u32(Bsm);

    auto load_tile = [&](int chunk, int s) {
        const int k0 = chunk * 32;
#pragma unroll
        for (int it = 0; it < 4; it++) {
            int id  = it * 256 + tid;
            int row = id >> 3;
            int cc  = id & 7;
            uint32_t off = (uint32_t)((s * TILE_FLOATS + row * SM_STRIDE + cc * 4) * 4);
            const float* ga = A + (size_t)(brow + row) * K + k0 + cc * 4;
            asm volatile("cp.async.cg.shared.global [%0], [%1], 16;"
                         :: "r"(sA + off), "l"(ga));
            const float* gb = Bt + (size_t)(bcol + row) * K + k0 + cc * 4;
            asm volatile("cp.async.cg.shared.global [%0], [%1], 16;"
                         :: "r"(sB + off), "l"(gb));
        }
        asm volatile("cp.async.commit_group;" ::: "memory");
    };

    load_tile(0, 0);
    load_tile(1, 1);

    for (int i = 0; i < NCH; i++) {
        const int s = i & 1;
        if (i < NCH - 1) asm volatile("cp.async.wait_group 1;" ::: "memory");
        else             asm volatile("cp.async.wait_group 0;" ::: "memory");
        __syncthreads();

        const float* as = Asm + s * TILE_FLOATS;
        const float* bs = Bsm + s * TILE_FLOATS;

#pragma unroll
        for (int kk = 0; kk < 4; kk++) {
            const int k0 = kk * 8;
            uint32_t af[4][4];
#pragma unroll
            for (int mt = 0; mt < 4; mt++) {
                const float* p = as + (wm + mt * 16 + g) * SM_STRIDE + k0 + t4;
                af[mt][0] = f2tf32(p[0]);
                af[mt][1] = f2tf32(p[8 * SM_STRIDE]);
                af[mt][2] = f2tf32(p[4]);
                af[mt][3] = f2tf32(p[8 * SM_STRIDE + 4]);
            }
            uint32_t bf[4][2];
#pragma unroll
            for (int nt = 0; nt < 4; nt++) {
                const float* p = bs + (wn + nt * 8 + g) * SM_STRIDE + k0 + t4;
                bf[nt][0] = f2tf32(p[0]);
                bf[nt][1] = f2tf32(p[4]);
            }
#pragma unroll
            for (int mt = 0; mt < 4; mt++)
#pragma unroll
                for (int nt = 0; nt < 4; nt++)
                    MMA_TF32(acc[mt][nt], af[mt], bf[nt][0], bf[nt][1]);
        }
        __syncthreads();
        if (i + 2 < NCH) load_tile(i + 2, s);
    }

#pragma unroll
    for (int mt = 0; mt < 4; mt++) {
        const int row0 = brow + wm + mt * 16 + g;
#pragma unroll
        for (int nt = 0; nt < 4; nt++) {
            const int col = bcol + wn + nt * 8 + t4 * 2;
            const float bx = bias[col], by = bias[col + 1];
#pragma unroll
            for (int hh = 0; hh < 2; hh++) {
                const int row = row0 + hh * 8;
                float vx = acc[mt][nt][2 * hh]     + bx;
                float vy = acc[mt][nt][2 * hh + 1] + by;
                if (GELU) {
                    vx = 0.5f * vx * (1.0f + erff(vx * 0.70710678118654752f));
                    vy = 0.5f * vy * (1.0f + erff(vy * 0.70710678118654752f));
                }
                size_t go = (size_t)row * N + col;
                if (RES) {
                    float2 rv = *(const float2*)&res[go];
                    vx += rv.x; vy += rv.y;
                }
                float2 o; o.x = vx; o.y = vy;
                *(float2*)&C[go] = o;
            }
        }
    }
}

// ---------------------------------------------------------------------------
// Tensor-core flash attention. Block = 64 queries x 1 head, 4 warps.
// QK^T and PV via m16n8k8 tf32; online softmax in registers; P via smem.
// ---------------------------------------------------------------------------
#define KSTR 68                         // stride (words): frag loads conflict-free
#define VSTR 72                         // stride (words) for V B-frag loads
#define ATT_SMEM_BYTES ((64 * KSTR /*Q*/ + 64 * KSTR /*P*/ + 2 * 64 * KSTR /*K*/ + 2 * 64 * VSTR /*V*/) * 4)

__global__ __launch_bounds__(128) void attention_mma_kernel(
    const float* __restrict__ qkv, float* __restrict__ out) {
    extern __shared__ __align__(16) float smf[];
    float* Qs  = smf;
    float* Ps  = Qs + 64 * KSTR;
    float* Ksm = Ps + 64 * KSTR;          // [2][64*KSTR]
    float* Vsm = Ksm + 2 * 64 * KSTR;     // [2][64*VSTR]

    const int b = blockIdx.z, h = blockIdx.y, qt = blockIdx.x;
    const int tid = threadIdx.x, wid = tid >> 5, lane = tid & 31;
    const int g = lane >> 2, t4 = lane & 3;

    const uint32_t sK = smem_u32(Ksm), sV = smem_u32(Vsm);

    const float* Qg = qkv + (size_t)(b * SEQ + qt * 64) * QKVN + h * HD;
    const float* Kg = qkv + (size_t)b * SEQ * QKVN + DIM     + h * HD;
    const float* Vg = qkv + (size_t)b * SEQ * QKVN + 2 * DIM + h * HD;

    // load Q tile (pre-scaled by 1/sqrt(hd))
#pragma unroll
    for (int it = 0; it < 8; it++) {
        int id = it * 128 + tid;
        int r = id >> 4, c4 = (id & 15) * 4;
        float4 v = *(const float4*)(Qg + (size_t)r * QKVN + c4);
        float* dst = Qs + r * KSTR + c4;
        dst[0] = v.x * 0.125f; dst[1] = v.y * 0.125f;
        dst[2] = v.z * 0.125f; dst[3] = v.w * 0.125f;
    }

    auto loadKV = [&](int kb, int s) {
#pragma unroll
        for (int it = 0; it < 8; it++) {
            int id = it * 128 + tid;
            int r = id >> 4, c4 = (id & 15) * 4;
            const float* gk = Kg + (size_t)(kb * 64 + r) * QKVN + c4;
            asm volatile("cp.async.cg.shared.global [%0], [%1], 16;"
                         :: "r"(sK + (uint32_t)((s * 64 * KSTR + r * KSTR + c4) * 4)), "l"(gk));
            const float* gv = Vg + (size_t)(kb * 64 + r) * QKVN + c4;
            asm volatile("cp.async.cg.shared.global [%0], [%1], 16;"
                         :: "r"(sV + (uint32_t)((s * 64 * VSTR + r * VSTR + c4) * 4)), "l"(gv));
        }
        asm volatile("cp.async.commit_group;" ::: "memory");
    };

    loadKV(0, 0);
    loadKV(1, 1);
    __syncthreads();                     // Qs visible

    // Q A-fragments (persist across all key tiles)
    const int m0row = wid * 16 + g;
    uint32_t af[8][4];
#pragma unroll
    for (int kt = 0; kt < 8; kt++) {
        const float* p = Qs + m0row * KSTR + kt * 8 + t4;
        af[kt][0] = f2tf32(p[0]);
        af[kt][1] = f2tf32(p[8 * KSTR]);
        af[kt][2] = f2tf32(p[4]);
        af[kt][3] = f2tf32(p[8 * KSTR + 4]);
    }

    float of[8][4];
#pragma unroll
    for (int nt = 0; nt < 8; nt++)
#pragma unroll
        for (int r = 0; r < 4; r++) of[nt][r] = 0.f;
    float m0 = -INFINITY, m1 = -INFINITY, l0 = 0.f, l1 = 0.f;

    for (int i = 0; i < 16; i++) {
        const int s = i & 1;
        if (i < 15) asm volatile("cp.async.wait_group 1;" ::: "memory");
        else        asm volatile("cp.async.wait_group 0;" ::: "memory");
        __syncthreads();

        const float* ks = Ksm + s * 64 * KSTR;
        const float* vs = Vsm + s * 64 * VSTR;

        // S = Q K^T
        float sf[8][4];
#pragma unroll
        for (int nt = 0; nt < 8; nt++)
#pragma unroll
            for (int r = 0; r < 4; r++) sf[nt][r] = 0.f;
#pragma unroll
        for (int kt = 0; kt < 8; kt++) {
#pragma unroll
            for (int nt = 0; nt < 8; nt++) {
                const float* p = ks + (nt * 8 + g) * KSTR + kt * 8 + t4;
                uint32_t b0 = f2tf32(p[0]);
                uint32_t b1 = f2tf32(p[4]);
                MMA_TF32(sf[nt], af[kt], b0, b1);
            }
        }

        // online softmax (rows g and g+8 of this warp's 16)
        float tm0 = -INFINITY, tm1 = -INFINITY;
#pragma unroll
        for (int nt = 0; nt < 8; nt++) {
            tm0 = fmaxf(tm0, fmaxf(sf[nt][0], sf[nt][1]));
            tm1 = fmaxf(tm1, fmaxf(sf[nt][2], sf[nt][3]));
        }
        tm0 = fmaxf(tm0, __shfl_xor_sync(0xffffffffu, tm0, 1));
        tm0 = fmaxf(tm0, __shfl_xor_sync(0xffffffffu, tm0, 2));
        tm1 = fmaxf(tm1, __shfl_xor_sync(0xffffffffu, tm1, 1));
        tm1 = fmaxf(tm1, __shfl_xor_sync(0xffffffffu, tm1, 2));
        const float nm0 = fmaxf(m0, tm0), nm1 = fmaxf(m1, tm1);
        const float a0 = __expf(m0 - nm0), a1 = __expf(m1 - nm1);

        float rs0 = 0.f, rs1 = 0.f;
        float* pp0 = Ps + m0row * KSTR + 2 * t4;
        float* pp1 = Ps + (m0row + 8) * KSTR + 2 * t4;
#pragma unroll
        for (int nt = 0; nt < 8; nt++) {
            float p0 = __expf(sf[nt][0] - nm0);
            float p1 = __expf(sf[nt][1] - nm0);
            float p2 = __expf(sf[nt][2] - nm1);
            float p3 = __expf(sf[nt][3] - nm1);
            rs0 += p0 + p1; rs1 += p2 + p3;
            pp0[nt * 8]     = p0; pp0[nt * 8 + 1] = p1;
            pp1[nt * 8]     = p2; pp1[nt * 8 + 1] = p3;
        }
        rs0 += __shfl_xor_sync(0xffffffffu, rs0, 1);
        rs0 += __shfl_xor_sync(0xffffffffu, rs0, 2);
        rs1 += __shfl_xor_sync(0xffffffffu, rs1, 1);
        rs1 += __shfl_xor_sync(0xffffffffu, rs1, 2);
        l0 = l0 * a0 + rs0;
        l1 = l1 * a1 + rs1;
#pragma unroll
        for (int nt = 0; nt < 8; nt++) {
            of[nt][0] *= a0; of[nt][1] *= a0;
            of[nt][2] *= a1; of[nt][3] *= a1;
        }
        m0 = nm0; m1 = nm1;
        __syncthreads();                 // P visible

        // O += P V
#pragma unroll
        for (int kt = 0; kt < 8; kt++) {
            const float* pp = Ps + m0row * KSTR + kt * 8 + t4;
            uint32_t pf[4];
            pf[0] = f2tf32(pp[0]);
            pf[1] = f2tf32(pp[8 * KSTR]);
            pf[2] = f2tf32(pp[4]);
            pf[3] = f2tf32(pp[8 * KSTR + 4]);
#pragma unroll
            for (int nt = 0; nt < 8; nt++) {
                const float* vp = vs + (kt * 8 + t4) * VSTR + nt * 8 + g;
                uint32_t b0 = f2tf32(vp[0]);
                uint32_t b1 = f2tf32(vp[4 * VSTR]);
                MMA_TF32(of[nt], pf, b0, b1);
            }
        }
        __syncthreads();                 // done with buffers + P
        if (i + 2 < 16) loadKV(i + 2, s);
    }

    // epilogue
    const float i0 = 1.f / l0, i1 = 1.f / l1;
    const int row = b * SEQ + qt * 64 + m0row;
#pragma unroll
    for (int nt = 0; nt < 8; nt++) {
        const int col = h * HD + nt * 8 + 2 * t4;
        float2 v0; v0.x = of[nt][0] * i0; v0.y = of[nt][1] * i0;
        *(float2*)&out[(size_t)row * DIM + col] = v0;
        float2 v1; v1.x = of[nt][2] * i1; v1.y = of[nt][3] * i1;
        *(float2*)&out[(size_t)(row + 8) * DIM + col] = v1;
    }
}

// ---------------------------------------------------------------------------
// Repack / transpose / layernorm
// ---------------------------------------------------------------------------
__global__ void repack_qkv_t_kernel(const float* __restrict__ Wq, const float* __restrict__ bq,
                                    const float* __restrict__ Wk, const float* __restrict__ bk,
                                    const float* __restrict__ Wv, const float* __restrict__ bv) {
    int idx = blockIdx.x * blockDim.x + threadIdx.x;
    const int total = QKVN * DIM;
    if (idx < total) {
        int n = idx / DIM;
        int d = idx % DIM;
        int t  = n / DIM;
        int h  = (n % DIM) / HD;
        int kk = n % HD;
        const float* W = (t == 0) ? Wq : (t == 1) ? Wk : Wv;
        g_wqkv_t[idx] = W[(h * DIM + d) * HD + kk];
    }
    if (idx < QKVN) {
        int t  = idx / DIM;
        int h  = (idx % DIM) / HD;
        int kk = idx % HD;
        const float* bb = (t == 0) ? bq : (t == 1) ? bk : bv;
        g_bqkv[idx] = bb[h * HD + kk];
    }
}

__global__ void transpose_kernel(const float* __restrict__ in, float* __restrict__ out,
                                 int R, int C) {
    __shared__ float t[32][33];
    int c0 = blockIdx.x * 32, r0 = blockIdx.y * 32;
    int x = c0 + threadIdx.x;
    for (int dy = threadIdx.y; dy < 32; dy += 8) {
        int r = r0 + dy;
        if (r < R && x < C) t[dy][threadIdx.x] = in[(size_t)r * C + x];
    }
    __syncthreads();
    int y = r0 + threadIdx.x;
    for (int dx = threadIdx.y; dx < 32; dx += 8) {
        int c = c0 + dx;
        if (c < C && y < R) out[(size_t)c * R + y] = t[threadIdx.x][dx];
    }
}

__global__ void layernorm_kernel(const float* __restrict__ X,
                                 const float* __restrict__ gamma,
                                 const float* __restrict__ beta,
                                 float* __restrict__ Y) {
    const int row = blockIdx.x;
    const float* x = X + (size_t)row * DIM;
    float*       y = Y + (size_t)row * DIM;
    __shared__ float red[256];
    int tid = threadIdx.x;

    float s = 0.f;
    for (int i = tid; i < DIM; i += 256) s += x[i];
    red[tid] = s; __syncthreads();
    for (int off = 128; off > 0; off >>= 1) {
        if (tid < off) red[tid] += red[tid + off];
        __syncthreads();
    }
    float mean = red[0] / (float)DIM;
    __syncthreads();

    float v = 0.f;
    for (int i = tid; i < DIM; i += 256) { float d = x[i] - mean; v += d * d; }
    red[tid] = v; __syncthreads();
    for (int off = 128; off > 0; off >>= 1) {
        if (tid < off) red[tid] += red[tid + off];
        __syncthreads();
    }
    float var = red[0] / (float)(DIM - 1);      // ddof = 1
    float inv = rsqrtf(var + LN_EPS);

    for (int i = tid; i < DIM; i += 256)
        y[i] = gamma[i] * (x[i] - mean) * inv + beta[i];
}

// ---------------------------------------------------------------------------
// Host launch
// ---------------------------------------------------------------------------
extern "C" void kernel_launch(void* const* d_in, const int* in_sizes, int n_in,
                              void* d_out, int out_size) {
    const float* x   = (const float*)d_in[0];
    const float* Wq  = (const float*)d_in[1];
    const float* bq  = (const float*)d_in[2];
    const float* Wk  = (const float*)d_in[3];
    const float* bk  = (const float*)d_in[4];
    const float* Wv  = (const float*)d_in[5];
    const float* bv  = (const float*)d_in[6];
    const float* Wo  = (const float*)d_in[7];
    const float* bo  = (const float*)d_in[8];
    const float* W1  = (const float*)d_in[9];
    const float* b1  = (const float*)d_in[10];
    const float* W2  = (const float*)d_in[11];
    const float* b2  = (const float*)d_in[12];
    const float* g1  = (const float*)d_in[13];
    const float* be1 = (const float*)d_in[14];
    const float* g2  = (const float*)d_in[15];
    const float* be2 = (const float*)d_in[16];
    float* out = (float*)d_out;

    float *xn, *qkv, *att, *y1, *y2, *hbuf, *wqkv_t, *bqkv, *wo_t, *w1_t, *w2_t;
    cudaGetSymbolAddress((void**)&xn,     g_xn);
    cudaGetSymbolAddress((void**)&qkv,    g_qkv);
    cudaGetSymbolAddress((void**)&att,    g_att);
    cudaGetSymbolAddress((void**)&y1,     g_y1);
    cudaGetSymbolAddress((void**)&y2,     g_y2);
    cudaGetSymbolAddress((void**)&hbuf,   g_h);
    cudaGetSymbolAddress((void**)&wqkv_t, g_wqkv_t);
    cudaGetSymbolAddress((void**)&bqkv,   g_bqkv);
    cudaGetSymbolAddress((void**)&wo_t,   g_wo_t);
    cudaGetSymbolAddress((void**)&w1_t,   g_w1_t);
    cudaGetSymbolAddress((void**)&w2_t,   g_w2_t);

    cudaFuncSetAttribute(mma_gemm_kernel<false, false>,
                         cudaFuncAttributeMaxDynamicSharedMemorySize, GEMM_SMEM_BYTES);
    cudaFuncSetAttribute(mma_gemm_kernel<false, true>,
                         cudaFuncAttributeMaxDynamicSharedMemorySize, GEMM_SMEM_BYTES);
    cudaFuncSetAttribute(mma_gemm_kernel<true, false>,
                         cudaFuncAttributeMaxDynamicSharedMemorySize, GEMM_SMEM_BYTES);
    cudaFuncSetAttribute(attention_mma_kernel,
                         cudaFuncAttributeMaxDynamicSharedMemorySize, ATT_SMEM_BYTES);

    // weight repacks (small; stay hot in L2)
    {
        int total = QKVN * DIM;
        repack_qkv_t_kernel<<<(total + 255) / 256, 256>>>(Wq, bq, Wk, bk, Wv, bv);
    }
    {
        dim3 blk(32, 8);
        transpose_kernel<<<dim3(DIM / 32, DIM / 32), blk>>>(Wo, wo_t, DIM, DIM);
        transpose_kernel<<<dim3(D4 / 32, DIM / 32), blk>>>(W1, w1_t, DIM, D4);
        transpose_kernel<<<dim3(DIM / 32, D4 / 32), blk>>>(W2, w2_t, D4, DIM);
    }

    // 1. ln1
    layernorm_kernel<<<BS, 256>>>(x, g1, be1, xn);
    // 2. fused QKV gemm
    mma_gemm_kernel<false, false><<<dim3(QKVN / 128, BS / 128), 256, GEMM_SMEM_BYTES>>>(
        xn, wqkv_t, bqkv, nullptr, qkv, BS, QKVN, DIM);
    // 3. attention (tensor-core flash)
    attention_mma_kernel<<<dim3(SEQ / 64, NH, 8), 128, ATT_SMEM_BYTES>>>(qkv, att);
    // 4. o-proj + residual
    mma_gemm_kernel<false, true><<<dim3(DIM / 128, BS / 128), 256, GEMM_SMEM_BYTES>>>(
        att, wo_t, bo, xn, y1, BS, DIM, DIM);
    // 5. ln2
    layernorm_kernel<<<BS, 256>>>(y1, g2, be2, y2);
    // 6. ffn up + gelu
    mma_gemm_kernel<true, false><<<dim3(D4 / 128, BS / 128), 256, GEMM_SMEM_BYTES>>>(
        y2, w1_t, b1, nullptr, hbuf, BS, D4, DIM);
    // 7. ffn down + residual
    mma_gemm_kernel<false, true><<<dim3(DIM / 128, BS / 128), 256, GEMM_SMEM_BYTES>>>(
        hbuf, w2_t, b2, y2, out, BS, DIM, D4);
}

// round 6
// speedup vs baseline: 3.8298x; 1.1609x over previous
#include <cuda_runtime.h>
#include <math.h>
#include <stdint.h>

// ---------------------------------------------------------------------------
// Problem dims (fixed): B=8, S=1024, D=768, H=12, hd=64
// ---------------------------------------------------------------------------
#define BS   8192        // B*S rows
#define DIM  768
#define D4   3072        // 4*D
#define QKVN 2304        // 3*D
#define NH   12
#define HD   64
#define SEQ  1024
#define LN_EPS 1e-5f

// ---------------------------------------------------------------------------
// Static device scratch (no allocations allowed)
// ---------------------------------------------------------------------------
__device__ float g_xn  [BS * DIM];     // ln1 output, tf32-rounded (residual 1)
__device__ float g_qkv [BS * QKVN];    // fused qkv (tf32-rounded)
__device__ float g_att [BS * DIM];     // attention out (tf32-rounded)
__device__ float g_y1  [BS * DIM];     // after o-proj + residual (full fp32)
__device__ float g_y2  [BS * DIM];     // ln2 output, tf32-rounded (residual 2)
__device__ float g_h   [BS * D4];      // ffn hidden (tf32-rounded)
__device__ float g_wqkv_t[QKVN * DIM]; // [N=2304, K=768], tf32-rounded
__device__ float g_bqkv[QKVN];
__device__ float g_wo_t[DIM * DIM];    // tf32-rounded
__device__ float g_w1_t[D4 * DIM];     // tf32-rounded
__device__ float g_w2_t[DIM * D4];     // tf32-rounded

__device__ __forceinline__ uint32_t f2tf32(float v) {
    uint32_t r;
    asm("cvt.rna.tf32.f32 %0, %1;" : "=r"(r) : "f"(v));
    return r;
}
__device__ __forceinline__ float tf32r(float v) {   // round-to-nearest tf32, as float
    return __uint_as_float(f2tf32(v));
}

__device__ __forceinline__ uint32_t smem_u32(const void* p) {
    uint32_t a;
    asm("{ .reg .u64 t; cvta.to.shared.u64 t, %1; cvt.u32.u64 %0, t; }"
        : "=r"(a) : "l"(p));
    return a;
}

#define MMA_TF32(acc, a, b0, b1)                                               \
    asm volatile(                                                              \
        "mma.sync.aligned.m16n8k8.row.col.f32.tf32.tf32.f32 "                  \
        "{%0,%1,%2,%3}, {%4,%5,%6,%7}, {%8,%9}, {%0,%1,%2,%3};"                \
        : "+f"((acc)[0]), "+f"((acc)[1]), "+f"((acc)[2]), "+f"((acc)[3])       \
        : "r"((a)[0]), "r"((a)[1]), "r"((a)[2]), "r"((a)[3]),                  \
          "r"(b0), "r"(b1))

// ---------------------------------------------------------------------------
// Warp-level tf32 tensor-core GEMM. Inputs MUST be tf32-pre-rounded;
// fragments are fed as raw fp32 bits (no cvt in the hot loop).
//   C[M,N] = A[M,K] @ Bt[N,K]^T + bias (+GELU) (+res) (+round-out)
// ---------------------------------------------------------------------------
#define SM_STRIDE 36
#define TILE_FLOATS (128 * SM_STRIDE)
#define GEMM_SMEM_BYTES (4 * TILE_FLOATS * 4)

template <bool GELU, bool RES, bool ROUT>
__global__ __launch_bounds__(256) void mma_gemm_kernel(
    const float* __restrict__ A, const float* __restrict__ Bt,
    const float* __restrict__ bias, const float* __restrict__ res,
    float* __restrict__ C, int M, int N, int K) {
    extern __shared__ __align__(16) float sm[];
    float* Asm = sm;
    float* Bsm = sm + 2 * TILE_FLOATS;

    const int tid  = threadIdx.x;
    const int wid  = tid >> 5;
    const int lane = tid & 31;
    const int g    = lane >> 2;
    const int t4   = lane & 3;
    const int wm   = (wid >> 2) * 64;
    const int wn   = (wid & 3) * 32;

    const int brow = blockIdx.y * 128;
    const int bcol = blockIdx.x * 128;
    const int NCH  = K >> 5;

    float acc[4][4][4];
#pragma unroll
    for (int mt = 0; mt < 4; mt++)
#pragma unroll
        for (int nt = 0; nt < 4; nt++)
#pragma unroll
            for (int r = 0; r < 4; r++) acc[mt][nt][r] = 0.f;

    const uint32_t sA = smem_u32(Asm);
    const uint32_t sB = smem_u32(Bsm);

    auto load_tile = [&](int chunk, int s) {
        const int k0 = chunk * 32;
#pragma unroll
        for (int it = 0; it < 4; it++) {
            int id  = it * 256 + tid;
            int row = id >> 3;
            int cc  = id & 7;
            uint32_t off = (uint32_t)((s * TILE_FLOATS + row * SM_STRIDE + cc * 4) * 4);
            const float* ga = A + (size_t)(brow + row) * K + k0 + cc * 4;
            asm volatile("cp.async.cg.shared.global [%0], [%1], 16;"
                         :: "r"(sA + off), "l"(ga));
            const float* gb = Bt + (size_t)(bcol + row) * K + k0 + cc * 4;
            asm volatile("cp.async.cg.shared.global [%0], [%1], 16;"
                         :: "r"(sB + off), "l"(gb));
        }
        asm volatile("cp.async.commit_group;" ::: "memory");
    };

    load_tile(0, 0);
    load_tile(1, 1);

    for (int i = 0; i < NCH; i++) {
        const int s = i & 1;
        if (i < NCH - 1) asm volatile("cp.async.wait_group 1;" ::: "memory");
        else             asm volatile("cp.async.wait_group 0;" ::: "memory");
        __syncthreads();

        const uint32_t* as = (const uint32_t*)(Asm + s * TILE_FLOATS);
        const uint32_t* bs = (const uint32_t*)(Bsm + s * TILE_FLOATS);

#pragma unroll
        for (int kk = 0; kk < 4; kk++) {
            const int k0 = kk * 8;
            uint32_t af[4][4];
#pragma unroll
            for (int mt = 0; mt < 4; mt++) {
                const uint32_t* p = as + (wm + mt * 16 + g) * SM_STRIDE + k0 + t4;
                af[mt][0] = p[0];
                af[mt][1] = p[8 * SM_STRIDE];
                af[mt][2] = p[4];
                af[mt][3] = p[8 * SM_STRIDE + 4];
            }
            uint32_t bf[4][2];
#pragma unroll
            for (int nt = 0; nt < 4; nt++) {
                const uint32_t* p = bs + (wn + nt * 8 + g) * SM_STRIDE + k0 + t4;
                bf[nt][0] = p[0];
                bf[nt][1] = p[4];
            }
#pragma unroll
            for (int mt = 0; mt < 4; mt++)
#pragma unroll
                for (int nt = 0; nt < 4; nt++)
                    MMA_TF32(acc[mt][nt], af[mt], bf[nt][0], bf[nt][1]);
        }
        __syncthreads();
        if (i + 2 < NCH) load_tile(i + 2, s);
    }

#pragma unroll
    for (int mt = 0; mt < 4; mt++) {
        const int row0 = brow + wm + mt * 16 + g;
#pragma unroll
        for (int nt = 0; nt < 4; nt++) {
            const int col = bcol + wn + nt * 8 + t4 * 2;
            const float bx = bias[col], by = bias[col + 1];
#pragma unroll
            for (int hh = 0; hh < 2; hh++) {
                const int row = row0 + hh * 8;
                float vx = acc[mt][nt][2 * hh]     + bx;
                float vy = acc[mt][nt][2 * hh + 1] + by;
                if (GELU) {
                    vx = 0.5f * vx * (1.0f + erff(vx * 0.70710678118654752f));
                    vy = 0.5f * vy * (1.0f + erff(vy * 0.70710678118654752f));
                }
                if (ROUT) { vx = tf32r(vx); vy = tf32r(vy); }
                size_t go = (size_t)row * N + col;
                if (RES) {
                    float2 rv = *(const float2*)&res[go];
                    vx += rv.x; vy += rv.y;
                }
                float2 o; o.x = vx; o.y = vy;
                *(float2*)&C[go] = o;
            }
        }
    }
}

// ---------------------------------------------------------------------------
// Tensor-core flash attention. qkv is tf32-pre-rounded, so all fragments
// are raw fp32 bits. P fed as raw bits (truncation; P in [0,1], err<=2^-11).
// ---------------------------------------------------------------------------
#define KSTR 68
#define VSTR 72
#define ATT_SMEM_BYTES ((64 * KSTR /*Q*/ + 64 * KSTR /*P*/ + 2 * 64 * KSTR /*K*/ + 2 * 64 * VSTR /*V*/) * 4)

__global__ __launch_bounds__(128) void attention_mma_kernel(
    const float* __restrict__ qkv, float* __restrict__ out) {
    extern __shared__ __align__(16) float smf[];
    float* Qs  = smf;
    float* Ps  = Qs + 64 * KSTR;
    float* Ksm = Ps + 64 * KSTR;
    float* Vsm = Ksm + 2 * 64 * KSTR;

    const int b = blockIdx.z, h = blockIdx.y, qt = blockIdx.x;
    const int tid = threadIdx.x, wid = tid >> 5, lane = tid & 31;
    const int g = lane >> 2, t4 = lane & 3;

    const uint32_t sK = smem_u32(Ksm), sV = smem_u32(Vsm);

    const float* Qg = qkv + (size_t)(b * SEQ + qt * 64) * QKVN + h * HD;
    const float* Kg = qkv + (size_t)b * SEQ * QKVN + DIM     + h * HD;
    const float* Vg = qkv + (size_t)b * SEQ * QKVN + 2 * DIM + h * HD;

    // load Q tile (x0.125 is exact: tf32-ness preserved)
#pragma unroll
    for (int it = 0; it < 8; it++) {
        int id = it * 128 + tid;
        int r = id >> 4, c4 = (id & 15) * 4;
        float4 v = *(const float4*)(Qg + (size_t)r * QKVN + c4);
        float* dst = Qs + r * KSTR + c4;
        dst[0] = v.x * 0.125f; dst[1] = v.y * 0.125f;
        dst[2] = v.z * 0.125f; dst[3] = v.w * 0.125f;
    }

    auto loadKV = [&](int kb, int s) {
#pragma unroll
        for (int it = 0; it < 8; it++) {
            int id = it * 128 + tid;
            int r = id >> 4, c4 = (id & 15) * 4;
            const float* gk = Kg + (size_t)(kb * 64 + r) * QKVN + c4;
            asm volatile("cp.async.cg.shared.global [%0], [%1], 16;"
                         :: "r"(sK + (uint32_t)((s * 64 * KSTR + r * KSTR + c4) * 4)), "l"(gk));
            const float* gv = Vg + (size_t)(kb * 64 + r) * QKVN + c4;
            asm volatile("cp.async.cg.shared.global [%0], [%1], 16;"
                         :: "r"(sV + (uint32_t)((s * 64 * VSTR + r * VSTR + c4) * 4)), "l"(gv));
        }
        asm volatile("cp.async.commit_group;" ::: "memory");
    };

    loadKV(0, 0);
    loadKV(1, 1);
    __syncthreads();

    // Q A-fragments (raw bits; persist across all key tiles)
    const int m0row = wid * 16 + g;
    uint32_t af[8][4];
#pragma unroll
    for (int kt = 0; kt < 8; kt++) {
        const uint32_t* p = (const uint32_t*)Qs + m0row * KSTR + kt * 8 + t4;
        af[kt][0] = p[0];
        af[kt][1] = p[8 * KSTR];
        af[kt][2] = p[4];
        af[kt][3] = p[8 * KSTR + 4];
    }

    float of[8][4];
#pragma unroll
    for (int nt = 0; nt < 8; nt++)
#pragma unroll
        for (int r = 0; r < 4; r++) of[nt][r] = 0.f;
    float m0 = -INFINITY, m1 = -INFINITY, l0 = 0.f, l1 = 0.f;

    for (int i = 0; i < 16; i++) {
        const int s = i & 1;
        if (i < 15) asm volatile("cp.async.wait_group 1;" ::: "memory");
        else        asm volatile("cp.async.wait_group 0;" ::: "memory");
        __syncthreads();

        const uint32_t* ks = (const uint32_t*)(Ksm + s * 64 * KSTR);
        const uint32_t* vs = (const uint32_t*)(Vsm + s * 64 * VSTR);

        // S = Q K^T
        float sf[8][4];
#pragma unroll
        for (int nt = 0; nt < 8; nt++)
#pragma unroll
            for (int r = 0; r < 4; r++) sf[nt][r] = 0.f;
#pragma unroll
        for (int kt = 0; kt < 8; kt++) {
#pragma unroll
            for (int nt = 0; nt < 8; nt++) {
                const uint32_t* p = ks + (nt * 8 + g) * KSTR + kt * 8 + t4;
                MMA_TF32(sf[nt], af[kt], p[0], p[4]);
            }
        }

        // online softmax
        float tm0 = -INFINITY, tm1 = -INFINITY;
#pragma unroll
        for (int nt = 0; nt < 8; nt++) {
            tm0 = fmaxf(tm0, fmaxf(sf[nt][0], sf[nt][1]));
            tm1 = fmaxf(tm1, fmaxf(sf[nt][2], sf[nt][3]));
        }
        tm0 = fmaxf(tm0, __shfl_xor_sync(0xffffffffu, tm0, 1));
        tm0 = fmaxf(tm0, __shfl_xor_sync(0xffffffffu, tm0, 2));
        tm1 = fmaxf(tm1, __shfl_xor_sync(0xffffffffu, tm1, 1));
        tm1 = fmaxf(tm1, __shfl_xor_sync(0xffffffffu, tm1, 2));
        const float nm0 = fmaxf(m0, tm0), nm1 = fmaxf(m1, tm1);
        const float a0 = __expf(m0 - nm0), a1 = __expf(m1 - nm1);

        float rs0 = 0.f, rs1 = 0.f;
        float* pp0 = Ps + m0row * KSTR + 2 * t4;
        float* pp1 = Ps + (m0row + 8) * KSTR + 2 * t4;
#pragma unroll
        for (int nt = 0; nt < 8; nt++) {
            float p0 = __expf(sf[nt][0] - nm0);
            float p1 = __expf(sf[nt][1] - nm0);
            float p2 = __expf(sf[nt][2] - nm1);
            float p3 = __expf(sf[nt][3] - nm1);
            rs0 += p0 + p1; rs1 += p2 + p3;
            pp0[nt * 8]     = p0; pp0[nt * 8 + 1] = p1;
            pp1[nt * 8]     = p2; pp1[nt * 8 + 1] = p3;
        }
        rs0 += __shfl_xor_sync(0xffffffffu, rs0, 1);
        rs0 += __shfl_xor_sync(0xffffffffu, rs0, 2);
        rs1 += __shfl_xor_sync(0xffffffffu, rs1, 1);
        rs1 += __shfl_xor_sync(0xffffffffu, rs1, 2);
        l0 = l0 * a0 + rs0;
        l1 = l1 * a1 + rs1;
#pragma unroll
        for (int nt = 0; nt < 8; nt++) {
            of[nt][0] *= a0; of[nt][1] *= a0;
            of[nt][2] *= a1; of[nt][3] *= a1;
        }
        m0 = nm0; m1 = nm1;
        __syncthreads();

        // O += P V   (P raw bits: truncation error <= 2^-11 on [0,1] values)
#pragma unroll
        for (int kt = 0; kt < 8; kt++) {
            const uint32_t* pp = (const uint32_t*)Ps + m0row * KSTR + kt * 8 + t4;
            uint32_t pf[4];
            pf[0] = pp[0];
            pf[1] = pp[8 * KSTR];
            pf[2] = pp[4];
            pf[3] = pp[8 * KSTR + 4];
#pragma unroll
            for (int nt = 0; nt < 8; nt++) {
                const uint32_t* vp = vs + (kt * 8 + t4) * VSTR + nt * 8 + g;
                MMA_TF32(of[nt], pf, vp[0], vp[4 * VSTR]);
            }
        }
        __syncthreads();
        if (i + 2 < 16) loadKV(i + 2, s);
    }

    // epilogue (round: feeds o-proj GEMM)
    const float i0 = 1.f / l0, i1 = 1.f / l1;
    const int row = b * SEQ + qt * 64 + m0row;
#pragma unroll
    for (int nt = 0; nt < 8; nt++) {
        const int col = h * HD + nt * 8 + 2 * t4;
        float2 v0; v0.x = tf32r(of[nt][0] * i0); v0.y = tf32r(of[nt][1] * i0);
        *(float2*)&out[(size_t)row * DIM + col] = v0;
        float2 v1; v1.x = tf32r(of[nt][2] * i1); v1.y = tf32r(of[nt][3] * i1);
        *(float2*)&out[(size_t)(row + 8) * DIM + col] = v1;
    }
}

// ---------------------------------------------------------------------------
// Repack Wq/Wk/Wv -> [3D, D] tf32-rounded; transpose weights tf32-rounded
// ---------------------------------------------------------------------------
__global__ void repack_qkv_t_kernel(const float* __restrict__ Wq, const float* __restrict__ bq,
                                    const float* __restrict__ Wk, const float* __restrict__ bk,
                                    const float* __restrict__ Wv, const float* __restrict__ bv) {
    int idx = blockIdx.x * blockDim.x + threadIdx.x;
    const int total = QKVN * DIM;
    if (idx < total) {
        int n = idx / DIM;
        int d = idx % DIM;
        int t  = n / DIM;
        int h  = (n % DIM) / HD;
        int kk = n % HD;
        const float* W = (t == 0) ? Wq : (t == 1) ? Wk : Wv;
        g_wqkv_t[idx] = tf32r(W[(h * DIM + d) * HD + kk]);
    }
    if (idx < QKVN) {
        int t  = idx / DIM;
        int h  = (idx % DIM) / HD;
        int kk = idx % HD;
        const float* bb = (t == 0) ? bq : (t == 1) ? bk : bv;
        g_bqkv[idx] = bb[h * HD + kk];
    }
}

__global__ void transpose_kernel(const float* __restrict__ in, float* __restrict__ out,
                                 int R, int C) {
    __shared__ float t[32][33];
    int c0 = blockIdx.x * 32, r0 = blockIdx.y * 32;
    int x = c0 + threadIdx.x;
    for (int dy = threadIdx.y; dy < 32; dy += 8) {
        int r = r0 + dy;
        if (r < R && x < C) t[dy][threadIdx.x] = in[(size_t)r * C + x];
    }
    __syncthreads();
    int y = r0 + threadIdx.x;
    for (int dx = threadIdx.y; dx < 32; dx += 8) {
        int c = c0 + dx;
        if (c < C && y < R) out[(size_t)c * R + y] = tf32r(t[threadIdx.x][dx]);
    }
}

// ---------------------------------------------------------------------------
// LayerNorm ddof=1, shuffle reductions, tf32-rounded output
// ---------------------------------------------------------------------------
__global__ __launch_bounds__(256) void layernorm_kernel(
    const float* __restrict__ X, const float* __restrict__ gamma,
    const float* __restrict__ beta, float* __restrict__ Y) {
    const int row = blockIdx.x;
    const float* x = X + (size_t)row * DIM;
    float*       y = Y + (size_t)row * DIM;
    const int tid = threadIdx.x, wid = tid >> 5, lane = tid & 31;
    __shared__ float red[8];

    float v0 = x[tid], v1 = x[tid + 256], v2 = x[tid + 512];
    float s = v0 + v1 + v2;
#pragma unroll
    for (int o = 16; o > 0; o >>= 1) s += __shfl_xor_sync(0xffffffffu, s, o);
    if (lane == 0) red[wid] = s;
    __syncthreads();
    if (tid < 32) {
        float t = (tid < 8) ? red[tid] : 0.f;
#pragma unroll
        for (int o = 4; o > 0; o >>= 1) t += __shfl_xor_sync(0xffffffffu, t, o);
        if (tid == 0) red[0] = t;
    }
    __syncthreads();
    const float mean = red[0] / (float)DIM;

    float d0 = v0 - mean, d1 = v1 - mean, d2 = v2 - mean;
    float vv = d0 * d0 + d1 * d1 + d2 * d2;
#pragma unroll
    for (int o = 16; o > 0; o >>= 1) vv += __shfl_xor_sync(0xffffffffu, vv, o);
    if (lane == 0) red[wid] = vv;
    __syncthreads();
    if (tid < 32) {
        float t = (tid < 8) ? red[tid] : 0.f;
#pragma unroll
        for (int o = 4; o > 0; o >>= 1) t += __shfl_xor_sync(0xffffffffu, t, o);
        if (tid == 0) red[0] = t;
    }
    __syncthreads();
    const float inv = rsqrtf(red[0] / (float)(DIM - 1) + LN_EPS);

    y[tid]       = tf32r(gamma[tid]       * d0 * inv + beta[tid]);
    y[tid + 256] = tf32r(gamma[tid + 256] * d1 * inv + beta[tid + 256]);
    y[tid + 512] = tf32r(gamma[tid + 512] * d2 * inv + beta[tid + 512]);
}

// ---------------------------------------------------------------------------
// Host launch
// ---------------------------------------------------------------------------
extern "C" void kernel_launch(void* const* d_in, const int* in_sizes, int n_in,
                              void* d_out, int out_size) {
    const float* x   = (const float*)d_in[0];
    const float* Wq  = (const float*)d_in[1];
    const float* bq  = (const float*)d_in[2];
    const float* Wk  = (const float*)d_in[3];
    const float* bk  = (const float*)d_in[4];
    const float* Wv  = (const float*)d_in[5];
    const float* bv  = (const float*)d_in[6];
    const float* Wo  = (const float*)d_in[7];
    const float* bo  = (const float*)d_in[8];
    const float* W1  = (const float*)d_in[9];
    const float* b1  = (const float*)d_in[10];
    const float* W2  = (const float*)d_in[11];
    const float* b2  = (const float*)d_in[12];
    const float* g1  = (const float*)d_in[13];
    const float* be1 = (const float*)d_in[14];
    const float* g2  = (const float*)d_in[15];
    const float* be2 = (const float*)d_in[16];
    float* out = (float*)d_out;

    float *xn, *qkv, *att, *y1, *y2, *hbuf, *wqkv_t, *bqkv, *wo_t, *w1_t, *w2_t;
    cudaGetSymbolAddress((void**)&xn,     g_xn);
    cudaGetSymbolAddress((void**)&qkv,    g_qkv);
    cudaGetSymbolAddress((void**)&att,    g_att);
    cudaGetSymbolAddress((void**)&y1,     g_y1);
    cudaGetSymbolAddress((void**)&y2,     g_y2);
    cudaGetSymbolAddress((void**)&hbuf,   g_h);
    cudaGetSymbolAddress((void**)&wqkv_t, g_wqkv_t);
    cudaGetSymbolAddress((void**)&bqkv,   g_bqkv);
    cudaGetSymbolAddress((void**)&wo_t,   g_wo_t);
    cudaGetSymbolAddress((void**)&w1_t,   g_w1_t);
    cudaGetSymbolAddress((void**)&w2_t,   g_w2_t);

    cudaFuncSetAttribute(mma_gemm_kernel<false, false, true>,
                         cudaFuncAttributeMaxDynamicSharedMemorySize, GEMM_SMEM_BYTES);
    cudaFuncSetAttribute(mma_gemm_kernel<false, true, false>,
                         cudaFuncAttributeMaxDynamicSharedMemorySize, GEMM_SMEM_BYTES);
    cudaFuncSetAttribute(mma_gemm_kernel<true, false, true>,
                         cudaFuncAttributeMaxDynamicSharedMemorySize, GEMM_SMEM_BYTES);
    cudaFuncSetAttribute(attention_mma_kernel,
                         cudaFuncAttributeMaxDynamicSharedMemorySize, ATT_SMEM_BYTES);

    // weight repacks (tf32-rounded; small, stay hot in L2)
    {
        int total = QKVN * DIM;
        repack_qkv_t_kernel<<<(total + 255) / 256, 256>>>(Wq, bq, Wk, bk, Wv, bv);
    }
    {
        dim3 blk(32, 8);
        transpose_kernel<<<dim3(DIM / 32, DIM / 32), blk>>>(Wo, wo_t, DIM, DIM);
        transpose_kernel<<<dim3(D4 / 32, DIM / 32), blk>>>(W1, w1_t, DIM, D4);
        transpose_kernel<<<dim3(DIM / 32, D4 / 32), blk>>>(W2, w2_t, D4, DIM);
    }

    // 1. ln1 (rounded out)
    layernorm_kernel<<<BS, 256>>>(x, g1, be1, xn);
    // 2. fused QKV gemm (rounded out: feeds attention)
    mma_gemm_kernel<false, false, true><<<dim3(QKVN / 128, BS / 128), 256, GEMM_SMEM_BYTES>>>(
        xn, wqkv_t, bqkv, nullptr, qkv, BS, QKVN, DIM);
    // 3. attention (rounded out: feeds o-proj)
    attention_mma_kernel<<<dim3(SEQ / 64, NH, 8), 128, ATT_SMEM_BYTES>>>(qkv, att);
    // 4. o-proj + residual (full precision out: feeds ln2 only)
    mma_gemm_kernel<false, true, false><<<dim3(DIM / 128, BS / 128), 256, GEMM_SMEM_BYTES>>>(
        att, wo_t, bo, xn, y1, BS, DIM, DIM);
    // 5. ln2 (rounded out)
    layernorm_kernel<<<BS, 256>>>(y1, g2, be2, y2);
    // 6. ffn up + gelu (rounded out: feeds ffn down)
    mma_gemm_kernel<true, false, true><<<dim3(D4 / 128, BS / 128), 256, GEMM_SMEM_BYTES>>>(
        y2, w1_t, b1, nullptr, hbuf, BS, D4, DIM);
    // 7. ffn down + residual (final output: full precision)
    mma_gemm_kernel<false, true, false><<<dim3(DIM / 128, BS / 128), 256, GEMM_SMEM_BYTES>>>(
        hbuf, w2_t, b2, y2, out, BS, DIM, D4);
}